// round 7
// baseline (speedup 1.0000x reference)
#include <cuda_runtime.h>
#include <math.h>
#include <stdint.h>

#define T  8192
#define H  512
#define E  8
#define IM 1024
#define IS 2048

#define BK   32
#define ASTR 36   // BK + 4 pad words; row stride 144B (16B aligned for cp.async)

// ---------------- device scratch (allocation-free) ----------------
__device__ int   g_cnt[E];
__device__ int   g_tok[E * T];
__device__ float g_wt[E * T];
__device__ float g_sgate[T];
__device__ float g_h[(size_t)E * T * IM];    // routed SwiGLU acts (tf32, K-interleaved)
__device__ float g_hs[(size_t)T * IS];       // shared SwiGLU acts (tf32, K-interleaved)
// pre-rounded tf32, K-interleaved copies of operands
__device__ float g_xr[(size_t)T * H];
__device__ float g_w1r[(size_t)E * IM * H];
__device__ float g_w3r[(size_t)E * IM * H];
__device__ float g_w2r[(size_t)E * H * IM];
__device__ float g_sw1r[(size_t)IS * H];
__device__ float g_sw3r[(size_t)IS * H];
__device__ float g_sw2r[(size_t)H * IS];

// ---------------- helpers ----------------
__device__ __forceinline__ uint32_t f2tf(float f) {
    uint32_t u; asm("cvt.rna.tf32.f32 %0, %1;" : "=r"(u) : "f"(f)); return u;
}
__device__ __forceinline__ void mma8(float* c,
        uint32_t a0, uint32_t a1, uint32_t a2, uint32_t a3,
        uint32_t b0, uint32_t b1) {
    asm volatile(
        "mma.sync.aligned.m16n8k8.row.col.f32.tf32.tf32.f32 "
        "{%0,%1,%2,%3}, {%4,%5,%6,%7}, {%8,%9}, {%0,%1,%2,%3};"
        : "+f"(c[0]), "+f"(c[1]), "+f"(c[2]), "+f"(c[3])
        : "r"(a0), "r"(a1), "r"(a2), "r"(a3), "r"(b0), "r"(b1));
}
__device__ __forceinline__ float silu_f(float v) { return v / (1.f + __expf(-v)); }
__device__ __forceinline__ uint32_t sptr(const void* p) {
    return (uint32_t)__cvta_generic_to_shared(p);
}
__device__ __forceinline__ void cp16(uint32_t dst, const void* src, int sz) {
    asm volatile("cp.async.cg.shared.global [%0], [%1], 16, %2;"
                 :: "r"(dst), "l"(src), "r"(sz));
}
#define CP_COMMIT() asm volatile("cp.async.commit_group;")
#define CP_WAIT1()  asm volatile("cp.async.wait_group 1;")

// storage position of logical index n (0..7) under K-interleave [0,4,1,5,2,6,3,7]
__device__ __forceinline__ int perm8(int n) { return ((n & 3) << 1) | (n >> 2); }

// ---------------- prologue: tf32 round + K-interleave (groups of 8) ----------------
__global__ void k_round_perm(const float* __restrict__ src, float* __restrict__ dst, int n8) {
    int i = blockIdx.x * blockDim.x + threadIdx.x;
    if (i >= n8) return;
    const float4* s4 = (const float4*)src;
    float4 v0 = s4[2 * i], v1 = s4[2 * i + 1];
    float4 o0, o1;
    o0.x = __uint_as_float(f2tf(v0.x));  // k0
    o0.y = __uint_as_float(f2tf(v1.x));  // k4
    o0.z = __uint_as_float(f2tf(v0.y));  // k1
    o0.w = __uint_as_float(f2tf(v1.y));  // k5
    o1.x = __uint_as_float(f2tf(v0.z));  // k2
    o1.y = __uint_as_float(f2tf(v1.z));  // k6
    o1.z = __uint_as_float(f2tf(v0.w));  // k3
    o1.w = __uint_as_float(f2tf(v1.w));  // k7
    float4* d4 = (float4*)dst;
    d4[2 * i] = o0; d4[2 * i + 1] = o1;
}

__global__ void k_zero_cnt() {
    if (threadIdx.x < E) g_cnt[threadIdx.x] = 0;
}

// One warp per token: router logits (fp32), softmax, top-2 dispatch, sigmoid gate.
__global__ void k_router(const float* __restrict__ x, const float* __restrict__ gw,
                         const float* __restrict__ sgw, float* __restrict__ logits_out) {
    const int warp = threadIdx.x >> 5;
    const int lane = threadIdx.x & 31;
    const int t = blockIdx.x * 8 + warp;
    if (t >= T) return;

    float xv[16];
    const float* xr = x + (size_t)t * H;
#pragma unroll
    for (int i = 0; i < 16; i++) xv[i] = xr[lane + 32 * i];

    float l[E];
#pragma unroll
    for (int e = 0; e < E; e++) {
        const float* w = gw + (size_t)e * H;
        float s = 0.f;
#pragma unroll
        for (int i = 0; i < 16; i++) s = fmaf(xv[i], w[lane + 32 * i], s);
#pragma unroll
        for (int off = 16; off > 0; off >>= 1) s += __shfl_xor_sync(0xffffffffu, s, off);
        l[e] = s;
    }
    float sd = 0.f;
#pragma unroll
    for (int i = 0; i < 16; i++) sd = fmaf(xv[i], sgw[lane + 32 * i], sd);
#pragma unroll
    for (int off = 16; off > 0; off >>= 1) sd += __shfl_xor_sync(0xffffffffu, sd, off);

    if (lane == 0) {
        if (logits_out) {
#pragma unroll
            for (int e = 0; e < E; e++) logits_out[(size_t)t * E + e] = l[e];
        }
        float m = l[0];
#pragma unroll
        for (int e = 1; e < E; e++) m = fmaxf(m, l[e]);
        float p[E], s = 0.f;
#pragma unroll
        for (int e = 0; e < E; e++) { p[e] = expf(l[e] - m); s += p[e]; }
        float inv = 1.f / s;
#pragma unroll
        for (int e = 0; e < E; e++) p[e] *= inv;
        int i1 = 0;
#pragma unroll
        for (int e = 1; e < E; e++) if (p[e] > p[i1]) i1 = e;
        int i2 = (i1 == 0) ? 1 : 0;
#pragma unroll
        for (int e = 0; e < E; e++) if (e != i1 && p[e] > p[i2]) i2 = e;

        int pos1 = atomicAdd(&g_cnt[i1], 1);
        g_tok[i1 * T + pos1] = t; g_wt[i1 * T + pos1] = p[i1];
        int pos2 = atomicAdd(&g_cnt[i2], 1);
        g_tok[i2 * T + pos2] = t; g_wt[i2 * T + pos2] = p[i2];

        g_sgate[t] = 1.f / (1.f + expf(-sd));
    }
}

// =====================================================================
// TF32 tensor-core GEMMs. Operands pre-rounded tf32 + K-interleaved in
// GMEM, so fragment reads are LDS.64 pairs. 2-stage cp.async pipeline.
// 256 threads = 8 warps laid out 4(m) x 2(n).
// =====================================================================

// Fragment access: for k-step ks, thread (qid,tig) reads uint2 at word
// offset row*ASTR + ks*8 + 2*tig -> (logical col tig, tig+4).
#define LOAD_A2(buf, row, ks) (*(const uint2*)&(buf)[(row) * ASTR + (ks) * 8 + 2 * tig])

// Routed up-projection (dual GEMM): h = silu(Xg @ w1e^T) * (Xg @ w3e^T)
__global__ __launch_bounds__(256) void k_up_routed_tc(
        const float* __restrict__ xq,
        const float* __restrict__ w1,
        const float* __restrict__ w3) {
    const int e = blockIdx.z;
    const int ne = g_cnt[e];
    const int row0 = blockIdx.y * 128;
    if (row0 >= ne) return;
    const int col0 = blockIdx.x * 64;
    const int* toks = g_tok + e * T;

    extern __shared__ uint32_t smem[];
    uint32_t* As  = smem;                       // 2 * 128*ASTR
    uint32_t* B1s = smem + 2 * 128 * ASTR;      // 2 * 64*ASTR
    uint32_t* B3s = B1s + 2 * 64 * ASTR;        // 2 * 64*ASTR

    const int tid = threadIdx.x;
    const int lane = tid & 31, wid = tid >> 5;
    const int qid = lane >> 2, tig = lane & 3;
    const int wm = wid & 3, wn = wid >> 2;
    const int lr = tid >> 3;
    const int lc = (tid & 7) * 4;

    int atok[4];
#pragma unroll
    for (int q = 0; q < 4; q++) {
        int r = row0 + lr + q * 32;
        atok[q] = (r < ne) ? toks[r] : -1;
    }
    const float* w1b = w1 + (size_t)e * IM * H + (size_t)col0 * H;
    const float* w3b = w3 + (size_t)e * IM * H + (size_t)col0 * H;

    float acc1[2][4][4], acc3[2][4][4];
#pragma unroll
    for (int mi = 0; mi < 2; mi++)
#pragma unroll
        for (int ni = 0; ni < 4; ni++)
#pragma unroll
            for (int r = 0; r < 4; r++) { acc1[mi][ni][r] = 0.f; acc3[mi][ni][r] = 0.f; }

    auto load_tile = [&](int buf, int k0) {
        uint32_t* Ab  = As  + buf * 128 * ASTR;
        uint32_t* B1b = B1s + buf * 64 * ASTR;
        uint32_t* B3b = B3s + buf * 64 * ASTR;
#pragma unroll
        for (int q = 0; q < 4; q++) {
            int r = lr + q * 32;
            const float* src = (atok[q] >= 0) ? (xq + (size_t)atok[q] * H + k0 + lc) : xq;
            cp16(sptr(&Ab[r * ASTR + lc]), src, (atok[q] >= 0) ? 16 : 0);
        }
#pragma unroll
        for (int q = 0; q < 2; q++) {
            int r = lr + q * 32;
            cp16(sptr(&B1b[r * ASTR + lc]), w1b + (size_t)r * H + k0 + lc, 16);
            cp16(sptr(&B3b[r * ASTR + lc]), w3b + (size_t)r * H + k0 + lc, 16);
        }
    };

    const int NK = H / BK;
    load_tile(0, 0);
    CP_COMMIT();
    for (int kt = 0; kt < NK; kt++) {
        int buf = kt & 1;
        if (kt + 1 < NK) load_tile(buf ^ 1, (kt + 1) * BK);
        CP_COMMIT();
        CP_WAIT1();
        __syncthreads();
        uint32_t* Ab  = As  + buf * 128 * ASTR;
        uint32_t* B1b = B1s + buf * 64 * ASTR;
        uint32_t* B3b = B3s + buf * 64 * ASTR;
#pragma unroll
        for (int ks = 0; ks < BK / 8; ks++) {
            uint32_t a[2][4];
#pragma unroll
            for (int mi = 0; mi < 2; mi++) {
                int mb = wm * 32 + mi * 16;
                uint2 lo = LOAD_A2(Ab, mb + qid, ks);
                uint2 hi = LOAD_A2(Ab, mb + qid + 8, ks);
                a[mi][0] = lo.x; a[mi][2] = lo.y;
                a[mi][1] = hi.x; a[mi][3] = hi.y;
            }
#pragma unroll
            for (int ni = 0; ni < 4; ni++) {
                int nr = wn * 32 + ni * 8 + qid;
                uint2 b1 = LOAD_A2(B1b, nr, ks);
                uint2 b3 = LOAD_A2(B3b, nr, ks);
#pragma unroll
                for (int mi = 0; mi < 2; mi++) {
                    mma8(acc1[mi][ni], a[mi][0], a[mi][1], a[mi][2], a[mi][3], b1.x, b1.y);
                    mma8(acc3[mi][ni], a[mi][0], a[mi][1], a[mi][2], a[mi][3], b3.x, b3.y);
                }
            }
        }
        __syncthreads();
    }
    // epilogue: write g_h K-interleaved (IM dim is K of the down GEMM)
    const int p0 = perm8(2 * tig), p1 = perm8(2 * tig + 1);
#pragma unroll
    for (int mi = 0; mi < 2; mi++) {
        int rbase = row0 + wm * 32 + mi * 16 + qid;
#pragma unroll
        for (int half = 0; half < 2; half++) {
            int r = rbase + half * 8;
            if (r >= ne) continue;
            float* orow = g_h + ((size_t)e * T + r) * IM + col0 + wn * 32;
#pragma unroll
            for (int ni = 0; ni < 4; ni++) {
                float v1a = acc1[mi][ni][half * 2], v1b = acc1[mi][ni][half * 2 + 1];
                float v3a = acc3[mi][ni][half * 2], v3b = acc3[mi][ni][half * 2 + 1];
                orow[ni * 8 + p0] = __uint_as_float(f2tf(silu_f(v1a) * v3a));
                orow[ni * 8 + p1] = __uint_as_float(f2tf(silu_f(v1b) * v3b));
            }
        }
    }
}

// Shared up-projection (dual GEMM): hs = silu(x @ sw1^T) * (x @ sw3^T)
__global__ __launch_bounds__(256) void k_up_shared_tc(
        const float* __restrict__ xq,
        const float* __restrict__ w1,
        const float* __restrict__ w3) {
    const int row0 = blockIdx.y * 128;
    const int col0 = blockIdx.x * 64;

    extern __shared__ uint32_t smem[];
    uint32_t* As  = smem;
    uint32_t* B1s = smem + 2 * 128 * ASTR;
    uint32_t* B3s = B1s + 2 * 64 * ASTR;

    const int tid = threadIdx.x;
    const int lane = tid & 31, wid = tid >> 5;
    const int qid = lane >> 2, tig = lane & 3;
    const int wm = wid & 3, wn = wid >> 2;
    const int lr = tid >> 3;
    const int lc = (tid & 7) * 4;

    const float* w1b = w1 + (size_t)col0 * H;
    const float* w3b = w3 + (size_t)col0 * H;

    float acc1[2][4][4], acc3[2][4][4];
#pragma unroll
    for (int mi = 0; mi < 2; mi++)
#pragma unroll
        for (int ni = 0; ni < 4; ni++)
#pragma unroll
            for (int r = 0; r < 4; r++) { acc1[mi][ni][r] = 0.f; acc3[mi][ni][r] = 0.f; }

    auto load_tile = [&](int buf, int k0) {
        uint32_t* Ab  = As  + buf * 128 * ASTR;
        uint32_t* B1b = B1s + buf * 64 * ASTR;
        uint32_t* B3b = B3s + buf * 64 * ASTR;
#pragma unroll
        for (int q = 0; q < 4; q++) {
            int r = lr + q * 32;
            cp16(sptr(&Ab[r * ASTR + lc]), xq + (size_t)(row0 + r) * H + k0 + lc, 16);
        }
#pragma unroll
        for (int q = 0; q < 2; q++) {
            int r = lr + q * 32;
            cp16(sptr(&B1b[r * ASTR + lc]), w1b + (size_t)r * H + k0 + lc, 16);
            cp16(sptr(&B3b[r * ASTR + lc]), w3b + (size_t)r * H + k0 + lc, 16);
        }
    };

    const int NK = H / BK;
    load_tile(0, 0);
    CP_COMMIT();
    for (int kt = 0; kt < NK; kt++) {
        int buf = kt & 1;
        if (kt + 1 < NK) load_tile(buf ^ 1, (kt + 1) * BK);
        CP_COMMIT();
        CP_WAIT1();
        __syncthreads();
        uint32_t* Ab  = As  + buf * 128 * ASTR;
        uint32_t* B1b = B1s + buf * 64 * ASTR;
        uint32_t* B3b = B3s + buf * 64 * ASTR;
#pragma unroll
        for (int ks = 0; ks < BK / 8; ks++) {
            uint32_t a[2][4];
#pragma unroll
            for (int mi = 0; mi < 2; mi++) {
                int mb = wm * 32 + mi * 16;
                uint2 lo = LOAD_A2(Ab, mb + qid, ks);
                uint2 hi = LOAD_A2(Ab, mb + qid + 8, ks);
                a[mi][0] = lo.x; a[mi][2] = lo.y;
                a[mi][1] = hi.x; a[mi][3] = hi.y;
            }
#pragma unroll
            for (int ni = 0; ni < 4; ni++) {
                int nr = wn * 32 + ni * 8 + qid;
                uint2 b1 = LOAD_A2(B1b, nr, ks);
                uint2 b3 = LOAD_A2(B3b, nr, ks);
#pragma unroll
                for (int mi = 0; mi < 2; mi++) {
                    mma8(acc1[mi][ni], a[mi][0], a[mi][1], a[mi][2], a[mi][3], b1.x, b1.y);
                    mma8(acc3[mi][ni], a[mi][0], a[mi][1], a[mi][2], a[mi][3], b3.x, b3.y);
                }
            }
        }
        __syncthreads();
    }
    const int p0 = perm8(2 * tig), p1 = perm8(2 * tig + 1);
#pragma unroll
    for (int mi = 0; mi < 2; mi++) {
        int rbase = row0 + wm * 32 + mi * 16 + qid;
#pragma unroll
        for (int half = 0; half < 2; half++) {
            int r = rbase + half * 8;
            float* orow = g_hs + (size_t)r * IS + col0 + wn * 32;
#pragma unroll
            for (int ni = 0; ni < 4; ni++) {
                float v1a = acc1[mi][ni][half * 2], v1b = acc1[mi][ni][half * 2 + 1];
                float v3a = acc3[mi][ni][half * 2], v3b = acc3[mi][ni][half * 2 + 1];
                orow[ni * 8 + p0] = __uint_as_float(f2tf(silu_f(v1a) * v3a));
                orow[ni * 8 + p1] = __uint_as_float(f2tf(silu_f(v1b) * v3b));
            }
        }
    }
}

// Routed down-projection + weighted scatter-add. BM=128, BN=128, warp tile 32x64.
__global__ __launch_bounds__(256) void k_down_routed_tc(
        const float* __restrict__ w2, float* __restrict__ out) {
    const int e = blockIdx.z;
    const int ne = g_cnt[e];
    const int row0 = blockIdx.y * 128;
    if (row0 >= ne) return;
    const int col0 = blockIdx.x * 128;

    extern __shared__ uint32_t smem[];
    uint32_t* As = smem;                   // 2 * 128*ASTR
    uint32_t* Bs = smem + 2 * 128 * ASTR;  // 2 * 128*ASTR

    const int tid = threadIdx.x;
    const int lane = tid & 31, wid = tid >> 5;
    const int qid = lane >> 2, tig = lane & 3;
    const int wm = wid & 3, wn = wid >> 2;
    const int lr = tid >> 3;
    const int lc = (tid & 7) * 4;

    const float* ab = g_h + (size_t)e * T * IM;
    const float* bb = w2 + (size_t)e * H * IM + (size_t)col0 * IM;

    float acc[2][8][4];
#pragma unroll
    for (int mi = 0; mi < 2; mi++)
#pragma unroll
        for (int ni = 0; ni < 8; ni++)
#pragma unroll
            for (int r = 0; r < 4; r++) acc[mi][ni][r] = 0.f;

    auto load_tile = [&](int buf, int k0) {
        uint32_t* Ab = As + buf * 128 * ASTR;
        uint32_t* Bb = Bs + buf * 128 * ASTR;
#pragma unroll
        for (int q = 0; q < 4; q++) {
            int r = lr + q * 32;
            cp16(sptr(&Ab[r * ASTR + lc]), ab + (size_t)(row0 + r) * IM + k0 + lc,
                 (row0 + r < ne) ? 16 : 0);
            cp16(sptr(&Bb[r * ASTR + lc]), bb + (size_t)r * IM + k0 + lc, 16);
        }
    };

    const int NK = IM / BK;
    load_tile(0, 0);
    CP_COMMIT();
    for (int kt = 0; kt < NK; kt++) {
        int buf = kt & 1;
        if (kt + 1 < NK) load_tile(buf ^ 1, (kt + 1) * BK);
        CP_COMMIT();
        CP_WAIT1();
        __syncthreads();
        uint32_t* Ab = As + buf * 128 * ASTR;
        uint32_t* Bb = Bs + buf * 128 * ASTR;
#pragma unroll
        for (int ks = 0; ks < BK / 8; ks++) {
            uint32_t a[2][4];
#pragma unroll
            for (int mi = 0; mi < 2; mi++) {
                int mb = wm * 32 + mi * 16;
                uint2 lo = LOAD_A2(Ab, mb + qid, ks);
                uint2 hi = LOAD_A2(Ab, mb + qid + 8, ks);
                a[mi][0] = lo.x; a[mi][2] = lo.y;
                a[mi][1] = hi.x; a[mi][3] = hi.y;
            }
#pragma unroll
            for (int ni = 0; ni < 8; ni++) {
                int nr = wn * 64 + ni * 8 + qid;
                uint2 b = LOAD_A2(Bb, nr, ks);
#pragma unroll
                for (int mi = 0; mi < 2; mi++)
                    mma8(acc[mi][ni], a[mi][0], a[mi][1], a[mi][2], a[mi][3], b.x, b.y);
            }
        }
        __syncthreads();
    }
#pragma unroll
    for (int mi = 0; mi < 2; mi++) {
        int rbase = row0 + wm * 32 + mi * 16 + qid;
#pragma unroll
        for (int half = 0; half < 2; half++) {
            int r = rbase + half * 8;
            if (r >= ne) continue;
            int t = g_tok[e * T + r];
            float wt = g_wt[e * T + r];
            float* orow = out + (size_t)t * H + col0 + wn * 64;
#pragma unroll
            for (int ni = 0; ni < 8; ni++) {
                int c = ni * 8 + 2 * tig;   // out H-dim NOT permuted
                atomicAdd(&orow[c],     wt * acc[mi][ni][half * 2]);
                atomicAdd(&orow[c + 1], wt * acc[mi][ni][half * 2 + 1]);
            }
        }
    }
}

// Final: out += sgate * (hs @ sw2^T). BM=128, BN=64, warp tile 32x32.
__global__ __launch_bounds__(256) void k_final_tc(
        const float* __restrict__ w2s, float* __restrict__ out) {
    const int row0 = blockIdx.y * 128;
    const int col0 = blockIdx.x * 64;

    extern __shared__ uint32_t smem[];
    uint32_t* As = smem;                   // 2 * 128*ASTR
    uint32_t* Bs = smem + 2 * 128 * ASTR;  // 2 * 64*ASTR

    const int tid = threadIdx.x;
    const int lane = tid & 31, wid = tid >> 5;
    const int qid = lane >> 2, tig = lane & 3;
    const int wm = wid & 3, wn = wid >> 2;
    const int lr = tid >> 3;
    const int lc = (tid & 7) * 4;

    const float* bb = w2s + (size_t)col0 * IS;

    float acc[2][4][4];
#pragma unroll
    for (int mi = 0; mi < 2; mi++)
#pragma unroll
        for (int ni = 0; ni < 4; ni++)
#pragma unroll
            for (int r = 0; r < 4; r++) acc[mi][ni][r] = 0.f;

    auto load_tile = [&](int buf, int k0) {
        uint32_t* Ab = As + buf * 128 * ASTR;
        uint32_t* Bb = Bs + buf * 64 * ASTR;
#pragma unroll
        for (int q = 0; q < 4; q++) {
            int r = lr + q * 32;
            cp16(sptr(&Ab[r * ASTR + lc]), g_hs + (size_t)(row0 + r) * IS + k0 + lc, 16);
        }
#pragma unroll
        for (int q = 0; q < 2; q++) {
            int r = lr + q * 32;
            cp16(sptr(&Bb[r * ASTR + lc]), bb + (size_t)r * IS + k0 + lc, 16);
        }
    };

    const int NK = IS / BK;
    load_tile(0, 0);
    CP_COMMIT();
    for (int kt = 0; kt < NK; kt++) {
        int buf = kt & 1;
        if (kt + 1 < NK) load_tile(buf ^ 1, (kt + 1) * BK);
        CP_COMMIT();
        CP_WAIT1();
        __syncthreads();
        uint32_t* Ab = As + buf * 128 * ASTR;
        uint32_t* Bb = Bs + buf * 64 * ASTR;
#pragma unroll
        for (int ks = 0; ks < BK / 8; ks++) {
            uint32_t a[2][4];
#pragma unroll
            for (int mi = 0; mi < 2; mi++) {
                int mb = wm * 32 + mi * 16;
                uint2 lo = LOAD_A2(Ab, mb + qid, ks);
                uint2 hi = LOAD_A2(Ab, mb + qid + 8, ks);
                a[mi][0] = lo.x; a[mi][2] = lo.y;
                a[mi][1] = hi.x; a[mi][3] = hi.y;
            }
#pragma unroll
            for (int ni = 0; ni < 4; ni++) {
                int nr = wn * 32 + ni * 8 + qid;
                uint2 b = LOAD_A2(Bb, nr, ks);
#pragma unroll
                for (int mi = 0; mi < 2; mi++)
                    mma8(acc[mi][ni], a[mi][0], a[mi][1], a[mi][2], a[mi][3], b.x, b.y);
            }
        }
        __syncthreads();
    }
#pragma unroll
    for (int mi = 0; mi < 2; mi++) {
        int rbase = row0 + wm * 32 + mi * 16 + qid;
#pragma unroll
        for (int half = 0; half < 2; half++) {
            int r = rbase + half * 8;
            float sg = g_sgate[r];
            float* orow = out + (size_t)r * H + col0 + wn * 32;
#pragma unroll
            for (int ni = 0; ni < 4; ni++) {
                int c = ni * 8 + 2 * tig;   // out H-dim NOT permuted
                orow[c]     += sg * acc[mi][ni][half * 2];
                orow[c + 1] += sg * acc[mi][ni][half * 2 + 1];
            }
        }
    }
}

// ---------------- launcher ----------------
extern "C" void kernel_launch(void* const* d_in, const int* in_sizes, int n_in,
                              void* d_out, int out_size) {
    const float* x   = (const float*)d_in[0];
    const float* gw  = (const float*)d_in[1];
    const float* w1  = (const float*)d_in[2];
    const float* w2  = (const float*)d_in[3];
    const float* w3  = (const float*)d_in[4];
    const float* sw1 = (const float*)d_in[5];
    const float* sw2 = (const float*)d_in[6];
    const float* sw3 = (const float*)d_in[7];
    const float* sgw = (const float*)d_in[8];

    float* out = (float*)d_out;
    float* logits = (out_size >= (int)((size_t)T * H + (size_t)T * E))
                        ? out + (size_t)T * H : nullptr;

    const int SM_UP    = 2 * (128 + 64 + 64) * ASTR * 4;  // 73728
    const int SM_DOWN  = 2 * (128 + 128) * ASTR * 4;      // 73728
    const int SM_FINAL = 2 * (128 + 64) * ASTR * 4;       // 55296

    cudaFuncSetAttribute(k_up_routed_tc,   cudaFuncAttributeMaxDynamicSharedMemorySize, SM_UP);
    cudaFuncSetAttribute(k_up_shared_tc,   cudaFuncAttributeMaxDynamicSharedMemorySize, SM_UP);
    cudaFuncSetAttribute(k_down_routed_tc, cudaFuncAttributeMaxDynamicSharedMemorySize, SM_DOWN);
    cudaFuncSetAttribute(k_final_tc,       cudaFuncAttributeMaxDynamicSharedMemorySize, SM_FINAL);

    void* p_xr;   cudaGetSymbolAddress(&p_xr,   g_xr);
    void* p_w1r;  cudaGetSymbolAddress(&p_w1r,  g_w1r);
    void* p_w3r;  cudaGetSymbolAddress(&p_w3r,  g_w3r);
    void* p_w2r;  cudaGetSymbolAddress(&p_w2r,  g_w2r);
    void* p_sw1r; cudaGetSymbolAddress(&p_sw1r, g_sw1r);
    void* p_sw3r; cudaGetSymbolAddress(&p_sw3r, g_sw3r);
    void* p_sw2r; cudaGetSymbolAddress(&p_sw2r, g_sw2r);

    k_zero_cnt<<<1, 32>>>();
    size_t nz = (size_t)T * H;
    if ((size_t)out_size < nz) nz = (size_t)out_size;
    cudaMemsetAsync(d_out, 0, nz * sizeof(float), 0);

    // pre-round + K-interleave all GEMM operands (memory-bound prologue)
    {
        const int TH = 256;
        int n8;
        n8 = T * H / 8;      k_round_perm<<<(n8 + TH - 1) / TH, TH>>>(x,   (float*)p_xr,   n8);
        n8 = E * IM * H / 8; k_round_perm<<<(n8 + TH - 1) / TH, TH>>>(w1,  (float*)p_w1r,  n8);
        n8 = E * IM * H / 8; k_round_perm<<<(n8 + TH - 1) / TH, TH>>>(w3,  (float*)p_w3r,  n8);
        n8 = E * H * IM / 8; k_round_perm<<<(n8 + TH - 1) / TH, TH>>>(w2,  (float*)p_w2r,  n8);
        n8 = IS * H / 8;     k_round_perm<<<(n8 + TH - 1) / TH, TH>>>(sw1, (float*)p_sw1r, n8);
        n8 = IS * H / 8;     k_round_perm<<<(n8 + TH - 1) / TH, TH>>>(sw3, (float*)p_sw3r, n8);
        n8 = H * IS / 8;     k_round_perm<<<(n8 + TH - 1) / TH, TH>>>(sw2, (float*)p_sw2r, n8);
    }

    k_router<<<T / 8, 256>>>(x, gw, sgw, logits);

    k_up_routed_tc  <<<dim3(IM / 64,  T / 128, E), 256, SM_UP>>>((const float*)p_xr, (const float*)p_w1r, (const float*)p_w3r);
    k_down_routed_tc<<<dim3(H / 128,  T / 128, E), 256, SM_DOWN>>>((const float*)p_w2r, out);

    k_up_shared_tc<<<dim3(IS / 64, T / 128), 256, SM_UP>>>((const float*)p_xr, (const float*)p_sw1r, (const float*)p_sw3r);
    k_final_tc    <<<dim3(H / 64,  T / 128), 256, SM_FINAL>>>((const float*)p_sw2r, out);
}

// round 8
// speedup vs baseline: 1.1661x; 1.1661x over previous
#include <cuda_runtime.h>
#include <math.h>
#include <stdint.h>

#define T  8192
#define H  512
#define E  8
#define IM 1024
#define IS 2048

#define BK   32
#define ASTR 36   // BK + 4 pad words; row stride 144B (16B aligned for cp.async)

// ---------------- device scratch (allocation-free) ----------------
__device__ int   g_cnt[E];
__device__ int   g_tok[E * T];
__device__ float g_wt[E * T];
__device__ float g_sgate[T];
__device__ float g_h[(size_t)E * T * IM];    // routed SwiGLU activations (pre-rounded tf32)
__device__ float g_hs[(size_t)T * IS];       // shared SwiGLU activations (pre-rounded tf32)
__device__ float g_xr[(size_t)T * H];
__device__ float g_w1r[(size_t)E * IM * H];
__device__ float g_w3r[(size_t)E * IM * H];
__device__ float g_w2r[(size_t)E * H * IM];
__device__ float g_sw1r[(size_t)IS * H];
__device__ float g_sw3r[(size_t)IS * H];
__device__ float g_sw2r[(size_t)H * IS];

// ---------------- helpers ----------------
__device__ __forceinline__ uint32_t f2tf(float f) {
    uint32_t u; asm("cvt.rna.tf32.f32 %0, %1;" : "=r"(u) : "f"(f)); return u;
}
__device__ __forceinline__ void mma8(float* c,
        uint32_t a0, uint32_t a1, uint32_t a2, uint32_t a3,
        uint32_t b0, uint32_t b1) {
    asm volatile(
        "mma.sync.aligned.m16n8k8.row.col.f32.tf32.tf32.f32 "
        "{%0,%1,%2,%3}, {%4,%5,%6,%7}, {%8,%9}, {%0,%1,%2,%3};"
        : "+f"(c[0]), "+f"(c[1]), "+f"(c[2]), "+f"(c[3])
        : "r"(a0), "r"(a1), "r"(a2), "r"(a3), "r"(b0), "r"(b1));
}
__device__ __forceinline__ float silu_f(float v) { return v / (1.f + __expf(-v)); }
__device__ __forceinline__ uint32_t sptr(const void* p) {
    return (uint32_t)__cvta_generic_to_shared(p);
}
__device__ __forceinline__ void cp16(uint32_t dst, const void* src, int sz) {
    asm volatile("cp.async.cg.shared.global [%0], [%1], 16, %2;"
                 :: "r"(dst), "l"(src), "r"(sz));
}
#define CP_COMMIT() asm volatile("cp.async.commit_group;")
#define CP_WAIT1()  asm volatile("cp.async.wait_group 1;")

// ---------------- prologue: elementwise tf32 pre-rounding ----------------
__global__ void k_round_tf32(const float* __restrict__ src, float* __restrict__ dst, int n4) {
    int i = blockIdx.x * blockDim.x + threadIdx.x;
    if (i >= n4) return;
    float4 v = ((const float4*)src)[i];
    float4 o;
    o.x = __uint_as_float(f2tf(v.x));
    o.y = __uint_as_float(f2tf(v.y));
    o.z = __uint_as_float(f2tf(v.z));
    o.w = __uint_as_float(f2tf(v.w));
    ((float4*)dst)[i] = o;
}

__global__ void k_zero_cnt() {
    if (threadIdx.x < E) g_cnt[threadIdx.x] = 0;
}

// One warp per token: router logits (fp32), softmax, top-2 dispatch, sigmoid gate.
__global__ void k_router(const float* __restrict__ x, const float* __restrict__ gw,
                         const float* __restrict__ sgw, float* __restrict__ logits_out) {
    const int warp = threadIdx.x >> 5;
    const int lane = threadIdx.x & 31;
    const int t = blockIdx.x * 8 + warp;
    if (t >= T) return;

    float xv[16];
    const float* xr = x + (size_t)t * H;
#pragma unroll
    for (int i = 0; i < 16; i++) xv[i] = xr[lane + 32 * i];

    float l[E];
#pragma unroll
    for (int e = 0; e < E; e++) {
        const float* w = gw + (size_t)e * H;
        float s = 0.f;
#pragma unroll
        for (int i = 0; i < 16; i++) s = fmaf(xv[i], w[lane + 32 * i], s);
#pragma unroll
        for (int off = 16; off > 0; off >>= 1) s += __shfl_xor_sync(0xffffffffu, s, off);
        l[e] = s;
    }
    float sd = 0.f;
#pragma unroll
    for (int i = 0; i < 16; i++) sd = fmaf(xv[i], sgw[lane + 32 * i], sd);
#pragma unroll
    for (int off = 16; off > 0; off >>= 1) sd += __shfl_xor_sync(0xffffffffu, sd, off);

    if (lane == 0) {
        if (logits_out) {
#pragma unroll
            for (int e = 0; e < E; e++) logits_out[(size_t)t * E + e] = l[e];
        }
        float m = l[0];
#pragma unroll
        for (int e = 1; e < E; e++) m = fmaxf(m, l[e]);
        float p[E], s = 0.f;
#pragma unroll
        for (int e = 0; e < E; e++) { p[e] = expf(l[e] - m); s += p[e]; }
        float inv = 1.f / s;
#pragma unroll
        for (int e = 0; e < E; e++) p[e] *= inv;
        int i1 = 0;
#pragma unroll
        for (int e = 1; e < E; e++) if (p[e] > p[i1]) i1 = e;
        int i2 = (i1 == 0) ? 1 : 0;
#pragma unroll
        for (int e = 0; e < E; e++) if (e != i1 && p[e] > p[i2]) i2 = e;

        int pos1 = atomicAdd(&g_cnt[i1], 1);
        g_tok[i1 * T + pos1] = t; g_wt[i1 * T + pos1] = p[i1];
        int pos2 = atomicAdd(&g_cnt[i2], 1);
        g_tok[i2 * T + pos2] = t; g_wt[i2 * T + pos2] = p[i2];

        g_sgate[t] = 1.f / (1.f + expf(-sd));
    }
}

// =====================================================================
// TF32 tensor-core GEMMs, operands pre-rounded tf32 in GMEM.
// 2-stage cp.async pipeline; 55.3 KB smem / ~65 regs per CTA so 3-4
// CTAs co-resident per SM hide barrier + cp.async wait phases.
// 256 threads = 8 warps laid out 4(m) x 2(n).
// =====================================================================

// Routed up-projection (dual GEMM): BM=128, BN=32, warp tile 32x16.
__global__ __launch_bounds__(256) void k_up_routed_tc(
        const float* __restrict__ xq,
        const float* __restrict__ w1,
        const float* __restrict__ w3) {
    const int e = blockIdx.z;
    const int ne = g_cnt[e];
    const int row0 = blockIdx.y * 128;
    if (row0 >= ne) return;
    const int col0 = blockIdx.x * 32;
    const int* toks = g_tok + e * T;

    extern __shared__ uint32_t smem[];
    uint32_t* As  = smem;                       // 2 * 128*ASTR
    uint32_t* B1s = smem + 2 * 128 * ASTR;      // 2 * 32*ASTR
    uint32_t* B3s = B1s + 2 * 32 * ASTR;        // 2 * 32*ASTR

    const int tid = threadIdx.x;
    const int lane = tid & 31, wid = tid >> 5;
    const int qid = lane >> 2, tig = lane & 3;
    const int wm = wid & 3, wn = wid >> 2;
    const int lr = tid >> 3;
    const int lc = (tid & 7) * 4;

    int atok[4];
#pragma unroll
    for (int q = 0; q < 4; q++) {
        int r = row0 + lr + q * 32;
        atok[q] = (r < ne) ? toks[r] : -1;
    }
    const float* w1b = w1 + (size_t)e * IM * H + (size_t)col0 * H;
    const float* w3b = w3 + (size_t)e * IM * H + (size_t)col0 * H;

    float acc1[2][2][4], acc3[2][2][4];
#pragma unroll
    for (int mi = 0; mi < 2; mi++)
#pragma unroll
        for (int ni = 0; ni < 2; ni++)
#pragma unroll
            for (int r = 0; r < 4; r++) { acc1[mi][ni][r] = 0.f; acc3[mi][ni][r] = 0.f; }

    auto load_tile = [&](int buf, int k0) {
        uint32_t* Ab  = As  + buf * 128 * ASTR;
        uint32_t* B1b = B1s + buf * 32 * ASTR;
        uint32_t* B3b = B3s + buf * 32 * ASTR;
#pragma unroll
        for (int q = 0; q < 4; q++) {
            int r = lr + q * 32;
            const float* src = (atok[q] >= 0) ? (xq + (size_t)atok[q] * H + k0 + lc) : xq;
            cp16(sptr(&Ab[r * ASTR + lc]), src, (atok[q] >= 0) ? 16 : 0);
        }
        cp16(sptr(&B1b[lr * ASTR + lc]), w1b + (size_t)lr * H + k0 + lc, 16);
        cp16(sptr(&B3b[lr * ASTR + lc]), w3b + (size_t)lr * H + k0 + lc, 16);
    };

    const int NK = H / BK;
    load_tile(0, 0);
    CP_COMMIT();
    for (int kt = 0; kt < NK; kt++) {
        int buf = kt & 1;
        if (kt + 1 < NK) load_tile(buf ^ 1, (kt + 1) * BK);
        CP_COMMIT();
        CP_WAIT1();
        __syncthreads();
        uint32_t* Ab  = As  + buf * 128 * ASTR;
        uint32_t* B1b = B1s + buf * 32 * ASTR;
        uint32_t* B3b = B3s + buf * 32 * ASTR;
#pragma unroll
        for (int ks = 0; ks < BK / 8; ks++) {
            const int kk = ks * 8 + tig;
            uint32_t a[2][4];
#pragma unroll
            for (int mi = 0; mi < 2; mi++) {
                int mb = wm * 32 + mi * 16;
                a[mi][0] = Ab[(mb + qid) * ASTR + kk];
                a[mi][1] = Ab[(mb + qid + 8) * ASTR + kk];
                a[mi][2] = Ab[(mb + qid) * ASTR + kk + 4];
                a[mi][3] = Ab[(mb + qid + 8) * ASTR + kk + 4];
            }
#pragma unroll
            for (int ni = 0; ni < 2; ni++) {
                int nb = (wn * 16 + ni * 8 + qid) * ASTR;
                uint32_t b10 = B1b[nb + kk], b11 = B1b[nb + kk + 4];
                uint32_t b30 = B3b[nb + kk], b31 = B3b[nb + kk + 4];
#pragma unroll
                for (int mi = 0; mi < 2; mi++) {
                    mma8(acc1[mi][ni], a[mi][0], a[mi][1], a[mi][2], a[mi][3], b10, b11);
                    mma8(acc3[mi][ni], a[mi][0], a[mi][1], a[mi][2], a[mi][3], b30, b31);
                }
            }
        }
        __syncthreads();
    }
#pragma unroll
    for (int mi = 0; mi < 2; mi++) {
        int rbase = row0 + wm * 32 + mi * 16 + qid;
#pragma unroll
        for (int half = 0; half < 2; half++) {
            int r = rbase + half * 8;
            if (r >= ne) continue;
            float* orow = g_h + ((size_t)e * T + r) * IM + col0 + wn * 16;
#pragma unroll
            for (int ni = 0; ni < 2; ni++) {
                float v1a = acc1[mi][ni][half * 2], v1b = acc1[mi][ni][half * 2 + 1];
                float v3a = acc3[mi][ni][half * 2], v3b = acc3[mi][ni][half * 2 + 1];
                int c = ni * 8 + 2 * tig;
                orow[c]     = __uint_as_float(f2tf(silu_f(v1a) * v3a));
                orow[c + 1] = __uint_as_float(f2tf(silu_f(v1b) * v3b));
            }
        }
    }
}

// Shared up-projection (dual GEMM): BM=128, BN=32, warp tile 32x16.
__global__ __launch_bounds__(256) void k_up_shared_tc(
        const float* __restrict__ xq,
        const float* __restrict__ w1,
        const float* __restrict__ w3) {
    const int row0 = blockIdx.y * 128;
    const int col0 = blockIdx.x * 32;

    extern __shared__ uint32_t smem[];
    uint32_t* As  = smem;
    uint32_t* B1s = smem + 2 * 128 * ASTR;
    uint32_t* B3s = B1s + 2 * 32 * ASTR;

    const int tid = threadIdx.x;
    const int lane = tid & 31, wid = tid >> 5;
    const int qid = lane >> 2, tig = lane & 3;
    const int wm = wid & 3, wn = wid >> 2;
    const int lr = tid >> 3;
    const int lc = (tid & 7) * 4;

    const float* w1b = w1 + (size_t)col0 * H;
    const float* w3b = w3 + (size_t)col0 * H;

    float acc1[2][2][4], acc3[2][2][4];
#pragma unroll
    for (int mi = 0; mi < 2; mi++)
#pragma unroll
        for (int ni = 0; ni < 2; ni++)
#pragma unroll
            for (int r = 0; r < 4; r++) { acc1[mi][ni][r] = 0.f; acc3[mi][ni][r] = 0.f; }

    auto load_tile = [&](int buf, int k0) {
        uint32_t* Ab  = As  + buf * 128 * ASTR;
        uint32_t* B1b = B1s + buf * 32 * ASTR;
        uint32_t* B3b = B3s + buf * 32 * ASTR;
#pragma unroll
        for (int q = 0; q < 4; q++) {
            int r = lr + q * 32;
            cp16(sptr(&Ab[r * ASTR + lc]), xq + (size_t)(row0 + r) * H + k0 + lc, 16);
        }
        cp16(sptr(&B1b[lr * ASTR + lc]), w1b + (size_t)lr * H + k0 + lc, 16);
        cp16(sptr(&B3b[lr * ASTR + lc]), w3b + (size_t)lr * H + k0 + lc, 16);
    };

    const int NK = H / BK;
    load_tile(0, 0);
    CP_COMMIT();
    for (int kt = 0; kt < NK; kt++) {
        int buf = kt & 1;
        if (kt + 1 < NK) load_tile(buf ^ 1, (kt + 1) * BK);
        CP_COMMIT();
        CP_WAIT1();
        __syncthreads();
        uint32_t* Ab  = As  + buf * 128 * ASTR;
        uint32_t* B1b = B1s + buf * 32 * ASTR;
        uint32_t* B3b = B3s + buf * 32 * ASTR;
#pragma unroll
        for (int ks = 0; ks < BK / 8; ks++) {
            const int kk = ks * 8 + tig;
            uint32_t a[2][4];
#pragma unroll
            for (int mi = 0; mi < 2; mi++) {
                int mb = wm * 32 + mi * 16;
                a[mi][0] = Ab[(mb + qid) * ASTR + kk];
                a[mi][1] = Ab[(mb + qid + 8) * ASTR + kk];
                a[mi][2] = Ab[(mb + qid) * ASTR + kk + 4];
                a[mi][3] = Ab[(mb + qid + 8) * ASTR + kk + 4];
            }
#pragma unroll
            for (int ni = 0; ni < 2; ni++) {
                int nb = (wn * 16 + ni * 8 + qid) * ASTR;
                uint32_t b10 = B1b[nb + kk], b11 = B1b[nb + kk + 4];
                uint32_t b30 = B3b[nb + kk], b31 = B3b[nb + kk + 4];
#pragma unroll
                for (int mi = 0; mi < 2; mi++) {
                    mma8(acc1[mi][ni], a[mi][0], a[mi][1], a[mi][2], a[mi][3], b10, b11);
                    mma8(acc3[mi][ni], a[mi][0], a[mi][1], a[mi][2], a[mi][3], b30, b31);
                }
            }
        }
        __syncthreads();
    }
#pragma unroll
    for (int mi = 0; mi < 2; mi++) {
        int rbase = row0 + wm * 32 + mi * 16 + qid;
#pragma unroll
        for (int half = 0; half < 2; half++) {
            int r = rbase + half * 8;
            float* orow = g_hs + (size_t)r * IS + col0 + wn * 16;
#pragma unroll
            for (int ni = 0; ni < 2; ni++) {
                float v1a = acc1[mi][ni][half * 2], v1b = acc1[mi][ni][half * 2 + 1];
                float v3a = acc3[mi][ni][half * 2], v3b = acc3[mi][ni][half * 2 + 1];
                int c = ni * 8 + 2 * tig;
                orow[c]     = __uint_as_float(f2tf(silu_f(v1a) * v3a));
                orow[c + 1] = __uint_as_float(f2tf(silu_f(v1b) * v3b));
            }
        }
    }
}

// Routed down-projection + weighted scatter-add. BM=128, BN=64, warp tile 32x32.
__global__ __launch_bounds__(256) void k_down_routed_tc(
        const float* __restrict__ w2, float* __restrict__ out) {
    const int e = blockIdx.z;
    const int ne = g_cnt[e];
    const int row0 = blockIdx.y * 128;
    if (row0 >= ne) return;
    const int col0 = blockIdx.x * 64;

    extern __shared__ uint32_t smem[];
    uint32_t* As = smem;                   // 2 * 128*ASTR
    uint32_t* Bs = smem + 2 * 128 * ASTR;  // 2 * 64*ASTR

    const int tid = threadIdx.x;
    const int lane = tid & 31, wid = tid >> 5;
    const int qid = lane >> 2, tig = lane & 3;
    const int wm = wid & 3, wn = wid >> 2;
    const int lr = tid >> 3;
    const int lc = (tid & 7) * 4;

    const float* ab = g_h + (size_t)e * T * IM;
    const float* bb = w2 + (size_t)e * H * IM + (size_t)col0 * IM;

    float acc[2][4][4];
#pragma unroll
    for (int mi = 0; mi < 2; mi++)
#pragma unroll
        for (int ni = 0; ni < 4; ni++)
#pragma unroll
            for (int r = 0; r < 4; r++) acc[mi][ni][r] = 0.f;

    auto load_tile = [&](int buf, int k0) {
        uint32_t* Ab = As + buf * 128 * ASTR;
        uint32_t* Bb = Bs + buf * 64 * ASTR;
#pragma unroll
        for (int q = 0; q < 4; q++) {
            int r = lr + q * 32;
            cp16(sptr(&Ab[r * ASTR + lc]), ab + (size_t)(row0 + r) * IM + k0 + lc,
                 (row0 + r < ne) ? 16 : 0);
        }
#pragma unroll
        for (int q = 0; q < 2; q++) {
            int r = lr + q * 32;
            cp16(sptr(&Bb[r * ASTR + lc]), bb + (size_t)r * IM + k0 + lc, 16);
        }
    };

    const int NK = IM / BK;
    load_tile(0, 0);
    CP_COMMIT();
    for (int kt = 0; kt < NK; kt++) {
        int buf = kt & 1;
        if (kt + 1 < NK) load_tile(buf ^ 1, (kt + 1) * BK);
        CP_COMMIT();
        CP_WAIT1();
        __syncthreads();
        uint32_t* Ab = As + buf * 128 * ASTR;
        uint32_t* Bb = Bs + buf * 64 * ASTR;
#pragma unroll
        for (int ks = 0; ks < BK / 8; ks++) {
            const int kk = ks * 8 + tig;
            uint32_t a[2][4];
#pragma unroll
            for (int mi = 0; mi < 2; mi++) {
                int mb = wm * 32 + mi * 16;
                a[mi][0] = Ab[(mb + qid) * ASTR + kk];
                a[mi][1] = Ab[(mb + qid + 8) * ASTR + kk];
                a[mi][2] = Ab[(mb + qid) * ASTR + kk + 4];
                a[mi][3] = Ab[(mb + qid + 8) * ASTR + kk + 4];
            }
#pragma unroll
            for (int ni = 0; ni < 4; ni++) {
                int nb = (wn * 32 + ni * 8 + qid) * ASTR;
                uint32_t b0 = Bs == nullptr ? 0 : Bb[nb + kk];
                uint32_t b1 = Bb[nb + kk + 4];
#pragma unroll
                for (int mi = 0; mi < 2; mi++)
                    mma8(acc[mi][ni], a[mi][0], a[mi][1], a[mi][2], a[mi][3], b0, b1);
            }
        }
        __syncthreads();
    }
#pragma unroll
    for (int mi = 0; mi < 2; mi++) {
        int rbase = row0 + wm * 32 + mi * 16 + qid;
#pragma unroll
        for (int half = 0; half < 2; half++) {
            int r = rbase + half * 8;
            if (r >= ne) continue;
            int t = g_tok[e * T + r];
            float wt = g_wt[e * T + r];
            float* orow = out + (size_t)t * H + col0 + wn * 32;
#pragma unroll
            for (int ni = 0; ni < 4; ni++) {
                int c = ni * 8 + 2 * tig;
                atomicAdd(&orow[c],     wt * acc[mi][ni][half * 2]);
                atomicAdd(&orow[c + 1], wt * acc[mi][ni][half * 2 + 1]);
            }
        }
    }
}

// Final: out += sgate * (hs @ sw2^T). BM=128, BN=64, warp tile 32x32.
__global__ __launch_bounds__(256) void k_final_tc(
        const float* __restrict__ w2s, float* __restrict__ out) {
    const int row0 = blockIdx.y * 128;
    const int col0 = blockIdx.x * 64;

    extern __shared__ uint32_t smem[];
    uint32_t* As = smem;                   // 2 * 128*ASTR
    uint32_t* Bs = smem + 2 * 128 * ASTR;  // 2 * 64*ASTR

    const int tid = threadIdx.x;
    const int lane = tid & 31, wid = tid >> 5;
    const int qid = lane >> 2, tig = lane & 3;
    const int wm = wid & 3, wn = wid >> 2;
    const int lr = tid >> 3;
    const int lc = (tid & 7) * 4;

    const float* bb = w2s + (size_t)col0 * IS;

    float acc[2][4][4];
#pragma unroll
    for (int mi = 0; mi < 2; mi++)
#pragma unroll
        for (int ni = 0; ni < 4; ni++)
#pragma unroll
            for (int r = 0; r < 4; r++) acc[mi][ni][r] = 0.f;

    auto load_tile = [&](int buf, int k0) {
        uint32_t* Ab = As + buf * 128 * ASTR;
        uint32_t* Bb = Bs + buf * 64 * ASTR;
#pragma unroll
        for (int q = 0; q < 4; q++) {
            int r = lr + q * 32;
            cp16(sptr(&Ab[r * ASTR + lc]), g_hs + (size_t)(row0 + r) * IS + k0 + lc, 16);
        }
#pragma unroll
        for (int q = 0; q < 2; q++) {
            int r = lr + q * 32;
            cp16(sptr(&Bb[r * ASTR + lc]), bb + (size_t)r * IS + k0 + lc, 16);
        }
    };

    const int NK = IS / BK;
    load_tile(0, 0);
    CP_COMMIT();
    for (int kt = 0; kt < NK; kt++) {
        int buf = kt & 1;
        if (kt + 1 < NK) load_tile(buf ^ 1, (kt + 1) * BK);
        CP_COMMIT();
        CP_WAIT1();
        __syncthreads();
        uint32_t* Ab = As + buf * 128 * ASTR;
        uint32_t* Bb = Bs + buf * 64 * ASTR;
#pragma unroll
        for (int ks = 0; ks < BK / 8; ks++) {
            const int kk = ks * 8 + tig;
            uint32_t a[2][4];
#pragma unroll
            for (int mi = 0; mi < 2; mi++) {
                int mb = wm * 32 + mi * 16;
                a[mi][0] = Ab[(mb + qid) * ASTR + kk];
                a[mi][1] = Ab[(mb + qid + 8) * ASTR + kk];
                a[mi][2] = Ab[(mb + qid) * ASTR + kk + 4];
                a[mi][3] = Ab[(mb + qid + 8) * ASTR + kk + 4];
            }
#pragma unroll
            for (int ni = 0; ni < 4; ni++) {
                int nb = (wn * 32 + ni * 8 + qid) * ASTR;
                uint32_t b0 = Bb[nb + kk], b1 = Bb[nb + kk + 4];
#pragma unroll
                for (int mi = 0; mi < 2; mi++)
                    mma8(acc[mi][ni], a[mi][0], a[mi][1], a[mi][2], a[mi][3], b0, b1);
            }
        }
        __syncthreads();
    }
#pragma unroll
    for (int mi = 0; mi < 2; mi++) {
        int rbase = row0 + wm * 32 + mi * 16 + qid;
#pragma unroll
        for (int half = 0; half < 2; half++) {
            int r = rbase + half * 8;
            float sg = g_sgate[r];
            float* orow = out + (size_t)r * H + col0 + wn * 32;
#pragma unroll
            for (int ni = 0; ni < 4; ni++) {
                int c = ni * 8 + 2 * tig;
                orow[c]     += sg * acc[mi][ni][half * 2];
                orow[c + 1] += sg * acc[mi][ni][half * 2 + 1];
            }
        }
    }
}

// ---------------- launcher ----------------
extern "C" void kernel_launch(void* const* d_in, const int* in_sizes, int n_in,
                              void* d_out, int out_size) {
    const float* x   = (const float*)d_in[0];
    const float* gw  = (const float*)d_in[1];
    const float* w1  = (const float*)d_in[2];
    const float* w2  = (const float*)d_in[3];
    const float* w3  = (const float*)d_in[4];
    const float* sw1 = (const float*)d_in[5];
    const float* sw2 = (const float*)d_in[6];
    const float* sw3 = (const float*)d_in[7];
    const float* sgw = (const float*)d_in[8];

    float* out = (float*)d_out;
    float* logits = (out_size >= (int)((size_t)T * H + (size_t)T * E))
                        ? out + (size_t)T * H : nullptr;

    const int SM_UP    = 2 * (128 + 32 + 32) * ASTR * 4;  // 55296
    const int SM_DOWN  = 2 * (128 + 64) * ASTR * 4;       // 55296
    const int SM_FINAL = 2 * (128 + 64) * ASTR * 4;       // 55296

    cudaFuncSetAttribute(k_up_routed_tc,   cudaFuncAttributeMaxDynamicSharedMemorySize, SM_UP);
    cudaFuncSetAttribute(k_up_shared_tc,   cudaFuncAttributeMaxDynamicSharedMemorySize, SM_UP);
    cudaFuncSetAttribute(k_down_routed_tc, cudaFuncAttributeMaxDynamicSharedMemorySize, SM_DOWN);
    cudaFuncSetAttribute(k_final_tc,       cudaFuncAttributeMaxDynamicSharedMemorySize, SM_FINAL);

    void* p_xr;   cudaGetSymbolAddress(&p_xr,   g_xr);
    void* p_w1r;  cudaGetSymbolAddress(&p_w1r,  g_w1r);
    void* p_w3r;  cudaGetSymbolAddress(&p_w3r,  g_w3r);
    void* p_w2r;  cudaGetSymbolAddress(&p_w2r,  g_w2r);
    void* p_sw1r; cudaGetSymbolAddress(&p_sw1r, g_sw1r);
    void* p_sw3r; cudaGetSymbolAddress(&p_sw3r, g_sw3r);
    void* p_sw2r; cudaGetSymbolAddress(&p_sw2r, g_sw2r);

    k_zero_cnt<<<1, 32>>>();
    size_t nz = (size_t)T * H;
    if ((size_t)out_size < nz) nz = (size_t)out_size;
    cudaMemsetAsync(d_out, 0, nz * sizeof(float), 0);

    {
        const int TH = 256;
        int n4;
        n4 = T * H / 4;      k_round_tf32<<<(n4 + TH - 1) / TH, TH>>>(x,   (float*)p_xr,   n4);
        n4 = E * IM * H / 4; k_round_tf32<<<(n4 + TH - 1) / TH, TH>>>(w1,  (float*)p_w1r,  n4);
        n4 = E * IM * H / 4; k_round_tf32<<<(n4 + TH - 1) / TH, TH>>>(w3,  (float*)p_w3r,  n4);
        n4 = E * H * IM / 4; k_round_tf32<<<(n4 + TH - 1) / TH, TH>>>(w2,  (float*)p_w2r,  n4);
        n4 = IS * H / 4;     k_round_tf32<<<(n4 + TH - 1) / TH, TH>>>(sw1, (float*)p_sw1r, n4);
        n4 = IS * H / 4;     k_round_tf32<<<(n4 + TH - 1) / TH, TH>>>(sw3, (float*)p_sw3r, n4);
        n4 = H * IS / 4;     k_round_tf32<<<(n4 + TH - 1) / TH, TH>>>(sw2, (float*)p_sw2r, n4);
    }

    k_router<<<T / 8, 256>>>(x, gw, sgw, logits);

    k_up_routed_tc  <<<dim3(IM / 32, T / 128, E), 256, SM_UP>>>((const float*)p_xr, (const float*)p_w1r, (const float*)p_w3r);
    k_down_routed_tc<<<dim3(H / 64,  T / 128, E), 256, SM_DOWN>>>((const float*)p_w2r, out);

    k_up_shared_tc<<<dim3(IS / 32, T / 128), 256, SM_UP>>>((const float*)p_xr, (const float*)p_sw1r, (const float*)p_sw3r);
    k_final_tc    <<<dim3(H / 64,  T / 128), 256, SM_FINAL>>>((const float*)p_sw2r, out);
}

// round 11
// speedup vs baseline: 2.0764x; 1.7807x over previous
#include <cuda_runtime.h>
#include <cuda_fp16.h>
#include <math.h>
#include <stdint.h>

#define T  8192
#define H  512
#define E  8
#define IM 1024
#define IS 2048

#define BKH  64   // K-chunk in halves (128 B per row)
#define ASTR 36   // words per row: 64 halves (32 words) + 4 pad words = 144 B

// ---------------- device scratch (allocation-free) ----------------
__device__ int    g_cnt[E];
__device__ int    g_tok[E * T];
__device__ float  g_wt[E * T];
__device__ float  g_sgate[T];
__device__ __align__(16) __half g_h[(size_t)E * T * IM];   // routed SwiGLU acts (fp16)
__device__ __align__(16) __half g_hs[(size_t)T * IS];      // shared SwiGLU acts (fp16)
__device__ __align__(16) __half g_xh[(size_t)T * H];
__device__ __align__(16) __half g_w1h[(size_t)E * IM * H];
__device__ __align__(16) __half g_w3h[(size_t)E * IM * H];
__device__ __align__(16) __half g_w2h[(size_t)E * H * IM];
__device__ __align__(16) __half g_sw1h[(size_t)IS * H];
__device__ __align__(16) __half g_sw3h[(size_t)IS * H];
__device__ __align__(16) __half g_sw2h[(size_t)H * IS];

// ---------------- helpers ----------------
__device__ __forceinline__ void mma16(float* c,
        uint32_t a0, uint32_t a1, uint32_t a2, uint32_t a3,
        uint32_t b0, uint32_t b1) {
    asm volatile(
        "mma.sync.aligned.m16n8k16.row.col.f32.f16.f16.f32 "
        "{%0,%1,%2,%3}, {%4,%5,%6,%7}, {%8,%9}, {%0,%1,%2,%3};"
        : "+f"(c[0]), "+f"(c[1]), "+f"(c[2]), "+f"(c[3])
        : "r"(a0), "r"(a1), "r"(a2), "r"(a3), "r"(b0), "r"(b1));
}
__device__ __forceinline__ float silu_f(float v) { return v / (1.f + __expf(-v)); }
__device__ __forceinline__ uint32_t sptr(const void* p) {
    return (uint32_t)__cvta_generic_to_shared(p);
}
__device__ __forceinline__ void cp16(uint32_t dst, const void* src, int sz) {
    asm volatile("cp.async.cg.shared.global [%0], [%1], 16, %2;"
                 :: "r"(dst), "l"(src), "r"(sz));
}
#define CP_COMMIT() asm volatile("cp.async.commit_group;")
#define CP_WAIT1()  asm volatile("cp.async.wait_group 1;")

// ---------------- prologue: fp32 -> fp16 conversion ----------------
__global__ void k_to_half(const float* __restrict__ src, __half* __restrict__ dst, int n8) {
    int i = blockIdx.x * blockDim.x + threadIdx.x;
    if (i >= n8) return;
    const float4* s4 = (const float4*)src;
    float4 v0 = s4[2 * i], v1 = s4[2 * i + 1];
    __half2 h0 = __floats2half2_rn(v0.x, v0.y);
    __half2 h1 = __floats2half2_rn(v0.z, v0.w);
    __half2 h2 = __floats2half2_rn(v1.x, v1.y);
    __half2 h3 = __floats2half2_rn(v1.z, v1.w);
    uint4 o;
    o.x = *(uint32_t*)&h0; o.y = *(uint32_t*)&h1;
    o.z = *(uint32_t*)&h2; o.w = *(uint32_t*)&h3;
    ((uint4*)dst)[i] = o;
}

__global__ void k_zero_cnt() {
    if (threadIdx.x < E) g_cnt[threadIdx.x] = 0;
}

// One warp per token: router logits (fp32), softmax, top-2 dispatch, sigmoid gate.
__global__ void k_router(const float* __restrict__ x, const float* __restrict__ gw,
                         const float* __restrict__ sgw, float* __restrict__ logits_out) {
    const int warp = threadIdx.x >> 5;
    const int lane = threadIdx.x & 31;
    const int t = blockIdx.x * 8 + warp;
    if (t >= T) return;

    float xv[16];
    const float* xr = x + (size_t)t * H;
#pragma unroll
    for (int i = 0; i < 16; i++) xv[i] = xr[lane + 32 * i];

    float l[E];
#pragma unroll
    for (int e = 0; e < E; e++) {
        const float* w = gw + (size_t)e * H;
        float s = 0.f;
#pragma unroll
        for (int i = 0; i < 16; i++) s = fmaf(xv[i], w[lane + 32 * i], s);
#pragma unroll
        for (int off = 16; off > 0; off >>= 1) s += __shfl_xor_sync(0xffffffffu, s, off);
        l[e] = s;
    }
    float sd = 0.f;
#pragma unroll
    for (int i = 0; i < 16; i++) sd = fmaf(xv[i], sgw[lane + 32 * i], sd);
#pragma unroll
    for (int off = 16; off > 0; off >>= 1) sd += __shfl_xor_sync(0xffffffffu, sd, off);

    if (lane == 0) {
        if (logits_out) {
#pragma unroll
            for (int e = 0; e < E; e++) logits_out[(size_t)t * E + e] = l[e];
        }
        float m = l[0];
#pragma unroll
        for (int e = 1; e < E; e++) m = fmaxf(m, l[e]);
        float p[E], s = 0.f;
#pragma unroll
        for (int e = 0; e < E; e++) { p[e] = expf(l[e] - m); s += p[e]; }
        float inv = 1.f / s;
#pragma unroll
        for (int e = 0; e < E; e++) p[e] *= inv;
        int i1 = 0;
#pragma unroll
        for (int e = 1; e < E; e++) if (p[e] > p[i1]) i1 = e;
        int i2 = (i1 == 0) ? 1 : 0;
#pragma unroll
        for (int e = 0; e < E; e++) if (e != i1 && p[e] > p[i2]) i2 = e;

        int pos1 = atomicAdd(&g_cnt[i1], 1);
        g_tok[i1 * T + pos1] = t; g_wt[i1 * T + pos1] = p[i1];
        int pos2 = atomicAdd(&g_cnt[i2], 1);
        g_tok[i2 * T + pos2] = t; g_wt[i2 * T + pos2] = p[i2];

        g_sgate[t] = 1.f / (1.f + expf(-sd));
    }
}

// =====================================================================
// FP16 tensor-core GEMMs (m16n8k16, fp32 accumulate). Operands are
// fp16 in GMEM. K-chunk = 64 halves (128 B/row), 2-stage cp.async
// pipeline, 55.3 KB smem -> 3 CTAs/SM. 256 threads = 8 warps, 4(m)x2(n).
// Fragment LDS addressing identical to the tf32 variant: word kk and
// kk+4 now carry half-pairs (k,k+1) and (k+8,k+9).
// =====================================================================

// Routed up-projection (dual GEMM): BM=128, BN=32, warp tile 32x16.
__global__ __launch_bounds__(256) void k_up_routed_tc(
        const __half* __restrict__ xq,
        const __half* __restrict__ w1,
        const __half* __restrict__ w3) {
    const int e = blockIdx.z;
    const int ne = g_cnt[e];
    const int row0 = blockIdx.y * 128;
    if (row0 >= ne) return;
    const int col0 = blockIdx.x * 32;
    const int* toks = g_tok + e * T;

    extern __shared__ uint32_t smem[];
    uint32_t* As  = smem;                       // 2 * 128*ASTR
    uint32_t* B1s = smem + 2 * 128 * ASTR;      // 2 * 32*ASTR
    uint32_t* B3s = B1s + 2 * 32 * ASTR;        // 2 * 32*ASTR

    const int tid = threadIdx.x;
    const int lane = tid & 31, wid = tid >> 5;
    const int qid = lane >> 2, tig = lane & 3;
    const int wm = wid & 3, wn = wid >> 2;
    const int lr = tid >> 3;          // loader row 0..31
    const int lch = (tid & 7) * 8;    // loader col in halves (16B chunk)
    const int lcw = (tid & 7) * 4;    // same in words

    int atok[4];
#pragma unroll
    for (int q = 0; q < 4; q++) {
        int r = row0 + lr + q * 32;
        atok[q] = (r < ne) ? toks[r] : -1;
    }
    const __half* w1b = w1 + (size_t)e * IM * H + (size_t)col0 * H;
    const __half* w3b = w3 + (size_t)e * IM * H + (size_t)col0 * H;

    float acc1[2][2][4], acc3[2][2][4];
#pragma unroll
    for (int mi = 0; mi < 2; mi++)
#pragma unroll
        for (int ni = 0; ni < 2; ni++)
#pragma unroll
            for (int r = 0; r < 4; r++) { acc1[mi][ni][r] = 0.f; acc3[mi][ni][r] = 0.f; }

    auto load_tile = [&](int buf, int k0) {
        uint32_t* Ab  = As  + buf * 128 * ASTR;
        uint32_t* B1b = B1s + buf * 32 * ASTR;
        uint32_t* B3b = B3s + buf * 32 * ASTR;
#pragma unroll
        for (int q = 0; q < 4; q++) {
            int r = lr + q * 32;
            const __half* src = (atok[q] >= 0) ? (xq + (size_t)atok[q] * H + k0 + lch) : xq;
            cp16(sptr(&Ab[r * ASTR + lcw]), src, (atok[q] >= 0) ? 16 : 0);
        }
        cp16(sptr(&B1b[lr * ASTR + lcw]), w1b + (size_t)lr * H + k0 + lch, 16);
        cp16(sptr(&B3b[lr * ASTR + lcw]), w3b + (size_t)lr * H + k0 + lch, 16);
    };

    const int NK = H / BKH;   // 8
    load_tile(0, 0);
    CP_COMMIT();
    for (int kt = 0; kt < NK; kt++) {
        int buf = kt & 1;
        if (kt + 1 < NK) load_tile(buf ^ 1, (kt + 1) * BKH);
        CP_COMMIT();
        CP_WAIT1();
        __syncthreads();
        uint32_t* Ab  = As  + buf * 128 * ASTR;
        uint32_t* B1b = B1s + buf * 32 * ASTR;
        uint32_t* B3b = B3s + buf * 32 * ASTR;
#pragma unroll
        for (int ks = 0; ks < 4; ks++) {          // 4 x K=16
            const int kk = ks * 8 + tig;
            uint32_t a[2][4];
#pragma unroll
            for (int mi = 0; mi < 2; mi++) {
                int mb = wm * 32 + mi * 16;
                a[mi][0] = Ab[(mb + qid) * ASTR + kk];
                a[mi][1] = Ab[(mb + qid + 8) * ASTR + kk];
                a[mi][2] = Ab[(mb + qid) * ASTR + kk + 4];
                a[mi][3] = Ab[(mb + qid + 8) * ASTR + kk + 4];
            }
#pragma unroll
            for (int ni = 0; ni < 2; ni++) {
                int nb = (wn * 16 + ni * 8 + qid) * ASTR;
                uint32_t b10 = B1b[nb + kk], b11 = B1b[nb + kk + 4];
                uint32_t b30 = B3b[nb + kk], b31 = B3b[nb + kk + 4];
#pragma unroll
                for (int mi = 0; mi < 2; mi++) {
                    mma16(acc1[mi][ni], a[mi][0], a[mi][1], a[mi][2], a[mi][3], b10, b11);
                    mma16(acc3[mi][ni], a[mi][0], a[mi][1], a[mi][2], a[mi][3], b30, b31);
                }
            }
        }
        __syncthreads();
    }
#pragma unroll
    for (int mi = 0; mi < 2; mi++) {
        int rbase = row0 + wm * 32 + mi * 16 + qid;
#pragma unroll
        for (int half = 0; half < 2; half++) {
            int r = rbase + half * 8;
            if (r >= ne) continue;
            __half* orow = g_h + ((size_t)e * T + r) * IM + col0 + wn * 16;
#pragma unroll
            for (int ni = 0; ni < 2; ni++) {
                float v1a = acc1[mi][ni][half * 2], v1b = acc1[mi][ni][half * 2 + 1];
                float v3a = acc3[mi][ni][half * 2], v3b = acc3[mi][ni][half * 2 + 1];
                int c = ni * 8 + 2 * tig;
                orow[c]     = __float2half_rn(silu_f(v1a) * v3a);
                orow[c + 1] = __float2half_rn(silu_f(v1b) * v3b);
            }
        }
    }
}

// Shared up-projection (dual GEMM): BM=128, BN=32, warp tile 32x16.
__global__ __launch_bounds__(256) void k_up_shared_tc(
        const __half* __restrict__ xq,
        const __half* __restrict__ w1,
        const __half* __restrict__ w3) {
    const int row0 = blockIdx.y * 128;
    const int col0 = blockIdx.x * 32;

    extern __shared__ uint32_t smem[];
    uint32_t* As  = smem;
    uint32_t* B1s = smem + 2 * 128 * ASTR;
    uint32_t* B3s = B1s + 2 * 32 * ASTR;

    const int tid = threadIdx.x;
    const int lane = tid & 31, wid = tid >> 5;
    const int qid = lane >> 2, tig = lane & 3;
    const int wm = wid & 3, wn = wid >> 2;
    const int lr = tid >> 3;
    const int lch = (tid & 7) * 8;
    const int lcw = (tid & 7) * 4;

    const __half* w1b = w1 + (size_t)col0 * H;
    const __half* w3b = w3 + (size_t)col0 * H;

    float acc1[2][2][4], acc3[2][2][4];
#pragma unroll
    for (int mi = 0; mi < 2; mi++)
#pragma unroll
        for (int ni = 0; ni < 2; ni++)
#pragma unroll
            for (int r = 0; r < 4; r++) { acc1[mi][ni][r] = 0.f; acc3[mi][ni][r] = 0.f; }

    auto load_tile = [&](int buf, int k0) {
        uint32_t* Ab  = As  + buf * 128 * ASTR;
        uint32_t* B1b = B1s + buf * 32 * ASTR;
        uint32_t* B3b = B3s + buf * 32 * ASTR;
#pragma unroll
        for (int q = 0; q < 4; q++) {
            int r = lr + q * 32;
            cp16(sptr(&Ab[r * ASTR + lcw]), xq + (size_t)(row0 + r) * H + k0 + lch, 16);
        }
        cp16(sptr(&B1b[lr * ASTR + lcw]), w1b + (size_t)lr * H + k0 + lch, 16);
        cp16(sptr(&B3b[lr * ASTR + lcw]), w3b + (size_t)lr * H + k0 + lch, 16);
    };

    const int NK = H / BKH;   // 8
    load_tile(0, 0);
    CP_COMMIT();
    for (int kt = 0; kt < NK; kt++) {
        int buf = kt & 1;
        if (kt + 1 < NK) load_tile(buf ^ 1, (kt + 1) * BKH);
        CP_COMMIT();
        CP_WAIT1();
        __syncthreads();
        uint32_t* Ab  = As  + buf * 128 * ASTR;
        uint32_t* B1b = B1s + buf * 32 * ASTR;
        uint32_t* B3b = B3s + buf * 32 * ASTR;
#pragma unroll
        for (int ks = 0; ks < 4; ks++) {
            const int kk = ks * 8 + tig;
            uint32_t a[2][4];
#pragma unroll
            for (int mi = 0; mi < 2; mi++) {
                int mb = wm * 32 + mi * 16;
                a[mi][0] = Ab[(mb + qid) * ASTR + kk];
                a[mi][1] = Ab[(mb + qid + 8) * ASTR + kk];
                a[mi][2] = Ab[(mb + qid) * ASTR + kk + 4];
                a[mi][3] = Ab[(mb + qid + 8) * ASTR + kk + 4];
            }
#pragma unroll
            for (int ni = 0; ni < 2; ni++) {
                int nb = (wn * 16 + ni * 8 + qid) * ASTR;
                uint32_t b10 = B1b[nb + kk], b11 = B1b[nb + kk + 4];
                uint32_t b30 = B3b[nb + kk], b31 = B3b[nb + kk + 4];
#pragma unroll
                for (int mi = 0; mi < 2; mi++) {
                    mma16(acc1[mi][ni], a[mi][0], a[mi][1], a[mi][2], a[mi][3], b10, b11);
                    mma16(acc3[mi][ni], a[mi][0], a[mi][1], a[mi][2], a[mi][3], b30, b31);
                }
            }
        }
        __syncthreads();
    }
#pragma unroll
    for (int mi = 0; mi < 2; mi++) {
        int rbase = row0 + wm * 32 + mi * 16 + qid;
#pragma unroll
        for (int half = 0; half < 2; half++) {
            int r = rbase + half * 8;
            __half* orow = g_hs + (size_t)r * IS + col0 + wn * 16;
#pragma unroll
            for (int ni = 0; ni < 2; ni++) {
                float v1a = acc1[mi][ni][half * 2], v1b = acc1[mi][ni][half * 2 + 1];
                float v3a = acc3[mi][ni][half * 2], v3b = acc3[mi][ni][half * 2 + 1];
                int c = ni * 8 + 2 * tig;
                orow[c]     = __float2half_rn(silu_f(v1a) * v3a);
                orow[c + 1] = __float2half_rn(silu_f(v1b) * v3b);
            }
        }
    }
}

// Routed down-projection + weighted scatter-add. BM=128, BN=64, warp tile 32x32.
__global__ __launch_bounds__(256) void k_down_routed_tc(
        const __half* __restrict__ w2, float* __restrict__ out) {
    const int e = blockIdx.z;
    const int ne = g_cnt[e];
    const int row0 = blockIdx.y * 128;
    if (row0 >= ne) return;
    const int col0 = blockIdx.x * 64;

    extern __shared__ uint32_t smem[];
    uint32_t* As = smem;                   // 2 * 128*ASTR
    uint32_t* Bs = smem + 2 * 128 * ASTR;  // 2 * 64*ASTR

    const int tid = threadIdx.x;
    const int lane = tid & 31, wid = tid >> 5;
    const int qid = lane >> 2, tig = lane & 3;
    const int wm = wid & 3, wn = wid >> 2;
    const int lr = tid >> 3;
    const int lch = (tid & 7) * 8;
    const int lcw = (tid & 7) * 4;

    const __half* ab = g_h + (size_t)e * T * IM;
    const __half* bb = w2 + (size_t)e * H * IM + (size_t)col0 * IM;

    float acc[2][4][4];
#pragma unroll
    for (int mi = 0; mi < 2; mi++)
#pragma unroll
        for (int ni = 0; ni < 4; ni++)
#pragma unroll
            for (int r = 0; r < 4; r++) acc[mi][ni][r] = 0.f;

    auto load_tile = [&](int buf, int k0) {
        uint32_t* Ab = As + buf * 128 * ASTR;
        uint32_t* Bb = Bs + buf * 64 * ASTR;
#pragma unroll
        for (int q = 0; q < 4; q++) {
            int r = lr + q * 32;
            cp16(sptr(&Ab[r * ASTR + lcw]), ab + (size_t)(row0 + r) * IM + k0 + lch,
                 (row0 + r < ne) ? 16 : 0);
        }
#pragma unroll
        for (int q = 0; q < 2; q++) {
            int r = lr + q * 32;
            cp16(sptr(&Bb[r * ASTR + lcw]), bb + (size_t)r * IM + k0 + lch, 16);
        }
    };

    const int NK = IM / BKH;   // 16
    load_tile(0, 0);
    CP_COMMIT();
    for (int kt = 0; kt < NK; kt++) {
        int buf = kt & 1;
        if (kt + 1 < NK) load_tile(buf ^ 1, (kt + 1) * BKH);
        CP_COMMIT();
        CP_WAIT1();
        __syncthreads();
        uint32_t* Ab = As + buf * 128 * ASTR;
        uint32_t* Bb = Bs + buf * 64 * ASTR;
#pragma unroll
        for (int ks = 0; ks < 4; ks++) {
            const int kk = ks * 8 + tig;
            uint32_t a[2][4];
#pragma unroll
            for (int mi = 0; mi < 2; mi++) {
                int mb = wm * 32 + mi * 16;
                a[mi][0] = Ab[(mb + qid) * ASTR + kk];
                a[mi][1] = Ab[(mb + qid + 8) * ASTR + kk];
                a[mi][2] = Ab[(mb + qid) * ASTR + kk + 4];
                a[mi][3] = Ab[(mb + qid + 8) * ASTR + kk + 4];
            }
#pragma unroll
            for (int ni = 0; ni < 4; ni++) {
                int nb = (wn * 32 + ni * 8 + qid) * ASTR;
                uint32_t b0 = Bb[nb + kk], b1 = Bb[nb + kk + 4];
#pragma unroll
                for (int mi = 0; mi < 2; mi++)
                    mma16(acc[mi][ni], a[mi][0], a[mi][1], a[mi][2], a[mi][3], b0, b1);
            }
        }
        __syncthreads();
    }
#pragma unroll
    for (int mi = 0; mi < 2; mi++) {
        int rbase = row0 + wm * 32 + mi * 16 + qid;
#pragma unroll
        for (int half = 0; half < 2; half++) {
            int r = rbase + half * 8;
            if (r >= ne) continue;
            int t = g_tok[e * T + r];
            float wt = g_wt[e * T + r];
            float* orow = out + (size_t)t * H + col0 + wn * 32;
#pragma unroll
            for (int ni = 0; ni < 4; ni++) {
                int c = ni * 8 + 2 * tig;
                atomicAdd(&orow[c],     wt * acc[mi][ni][half * 2]);
                atomicAdd(&orow[c + 1], wt * acc[mi][ni][half * 2 + 1]);
            }
        }
    }
}

// Final: out += sgate * (hs @ sw2^T). BM=128, BN=64, warp tile 32x32.
__global__ __launch_bounds__(256) void k_final_tc(
        const __half* __restrict__ w2s, float* __restrict__ out) {
    const int row0 = blockIdx.y * 128;
    const int col0 = blockIdx.x * 64;

    extern __shared__ uint32_t smem[];
    uint32_t* As = smem;                   // 2 * 128*ASTR
    uint32_t* Bs = smem + 2 * 128 * ASTR;  // 2 * 64*ASTR

    const int tid = threadIdx.x;
    const int lane = tid & 31, wid = tid >> 5;
    const int qid = lane >> 2, tig = lane & 3;
    const int wm = wid & 3, wn = wid >> 2;
    const int lr = tid >> 3;
    const int lch = (tid & 7) * 8;
    const int lcw = (tid & 7) * 4;

    const __half* bb = w2s + (size_t)col0 * IS;

    float acc[2][4][4];
#pragma unroll
    for (int mi = 0; mi < 2; mi++)
#pragma unroll
        for (int ni = 0; ni < 4; ni++)
#pragma unroll
            for (int r = 0; r < 4; r++) acc[mi][ni][r] = 0.f;

    auto load_tile = [&](int buf, int k0) {
        uint32_t* Ab = As + buf * 128 * ASTR;
        uint32_t* Bb = Bs + buf * 64 * ASTR;
#pragma unroll
        for (int q = 0; q < 4; q++) {
            int r = lr + q * 32;
            cp16(sptr(&Ab[r * ASTR + lcw]), g_hs + (size_t)(row0 + r) * IS + k0 + lch, 16);
        }
#pragma unroll
        for (int q = 0; q < 2; q++) {
            int r = lr + q * 32;
            cp16(sptr(&Bb[r * ASTR + lcw]), bb + (size_t)r * IS + k0 + lch, 16);
        }
    };

    const int NK = IS / BKH;   // 32
    load_tile(0, 0);
    CP_COMMIT();
    for (int kt = 0; kt < NK; kt++) {
        int buf = kt & 1;
        if (kt + 1 < NK) load_tile(buf ^ 1, (kt + 1) * BKH);
        CP_COMMIT();
        CP_WAIT1();
        __syncthreads();
        uint32_t* Ab = As + buf * 128 * ASTR;
        uint32_t* Bb = Bs + buf * 64 * ASTR;
#pragma unroll
        for (int ks = 0; ks < 4; ks++) {
            const int kk = ks * 8 + tig;
            uint32_t a[2][4];
#pragma unroll
            for (int mi = 0; mi < 2; mi++) {
                int mb = wm * 32 + mi * 16;
                a[mi][0] = Ab[(mb + qid) * ASTR + kk];
                a[mi][1] = Ab[(mb + qid + 8) * ASTR + kk];
                a[mi][2] = Ab[(mb + qid) * ASTR + kk + 4];
                a[mi][3] = Ab[(mb + qid + 8) * ASTR + kk + 4];
            }
#pragma unroll
            for (int ni = 0; ni < 4; ni++) {
                int nb = (wn * 32 + ni * 8 + qid) * ASTR;
                uint32_t b0 = Bb[nb + kk], b1 = Bb[nb + kk + 4];
#pragma unroll
                for (int mi = 0; mi < 2; mi++)
                    mma16(acc[mi][ni], a[mi][0], a[mi][1], a[mi][2], a[mi][3], b0, b1);
            }
        }
        __syncthreads();
    }
#pragma unroll
    for (int mi = 0; mi < 2; mi++) {
        int rbase = row0 + wm * 32 + mi * 16 + qid;
#pragma unroll
        for (int half = 0; half < 2; half++) {
            int r = rbase + half * 8;
            float sg = g_sgate[r];
            float* orow = out + (size_t)r * H + col0 + wn * 32;
#pragma unroll
            for (int ni = 0; ni < 4; ni++) {
                int c = ni * 8 + 2 * tig;
                orow[c]     += sg * acc[mi][ni][half * 2];
                orow[c + 1] += sg * acc[mi][ni][half * 2 + 1];
            }
        }
    }
}

// ---------------- launcher ----------------
extern "C" void kernel_launch(void* const* d_in, const int* in_sizes, int n_in,
                              void* d_out, int out_size) {
    const float* x   = (const float*)d_in[0];
    const float* gw  = (const float*)d_in[1];
    const float* w1  = (const float*)d_in[2];
    const float* w2  = (const float*)d_in[3];
    const float* w3  = (const float*)d_in[4];
    const float* sw1 = (const float*)d_in[5];
    const float* sw2 = (const float*)d_in[6];
    const float* sw3 = (const float*)d_in[7];
    const float* sgw = (const float*)d_in[8];

    float* out = (float*)d_out;
    float* logits = (out_size >= (int)((size_t)T * H + (size_t)T * E))
                        ? out + (size_t)T * H : nullptr;

    const int SM_UP   = 2 * (128 + 32 + 32) * ASTR * 4;  // 55296
    const int SM_GEMM = 2 * (128 + 64) * ASTR * 4;       // 55296

    cudaFuncSetAttribute(k_up_routed_tc,   cudaFuncAttributeMaxDynamicSharedMemorySize, SM_UP);
    cudaFuncSetAttribute(k_up_shared_tc,   cudaFuncAttributeMaxDynamicSharedMemorySize, SM_UP);
    cudaFuncSetAttribute(k_down_routed_tc, cudaFuncAttributeMaxDynamicSharedMemorySize, SM_GEMM);
    cudaFuncSetAttribute(k_final_tc,       cudaFuncAttributeMaxDynamicSharedMemorySize, SM_GEMM);

    void* p_xh;   cudaGetSymbolAddress(&p_xh,   g_xh);
    void* p_w1h;  cudaGetSymbolAddress(&p_w1h,  g_w1h);
    void* p_w3h;  cudaGetSymbolAddress(&p_w3h,  g_w3h);
    void* p_w2h;  cudaGetSymbolAddress(&p_w2h,  g_w2h);
    void* p_sw1h; cudaGetSymbolAddress(&p_sw1h, g_sw1h);
    void* p_sw3h; cudaGetSymbolAddress(&p_sw3h, g_sw3h);
    void* p_sw2h; cudaGetSymbolAddress(&p_sw2h, g_sw2h);

    k_zero_cnt<<<1, 32>>>();
    size_t nz = (size_t)T * H;
    if ((size_t)out_size < nz) nz = (size_t)out_size;
    cudaMemsetAsync(d_out, 0, nz * sizeof(float), 0);

    // fp32 -> fp16 conversion prologue (memory-bound)
    {
        const int TH = 256;
        int n8;
        n8 = T * H / 8;      k_to_half<<<(n8 + TH - 1) / TH, TH>>>(x,   (__half*)p_xh,   n8);
        n8 = E * IM * H / 8; k_to_half<<<(n8 + TH - 1) / TH, TH>>>(w1,  (__half*)p_w1h,  n8);
        n8 = E * IM * H / 8; k_to_half<<<(n8 + TH - 1) / TH, TH>>>(w3,  (__half*)p_w3h,  n8);
        n8 = E * H * IM / 8; k_to_half<<<(n8 + TH - 1) / TH, TH>>>(w2,  (__half*)p_w2h,  n8);
        n8 = IS * H / 8;     k_to_half<<<(n8 + TH - 1) / TH, TH>>>(sw1, (__half*)p_sw1h, n8);
        n8 = IS * H / 8;     k_to_half<<<(n8 + TH - 1) / TH, TH>>>(sw3, (__half*)p_sw3h, n8);
        n8 = H * IS / 8;     k_to_half<<<(n8 + TH - 1) / TH, TH>>>(sw2, (__half*)p_sw2h, n8);
    }

    k_router<<<T / 8, 256>>>(x, gw, sgw, logits);

    k_up_routed_tc  <<<dim3(IM / 32, T / 128, E), 256, SM_UP>>>((const __half*)p_xh, (const __half*)p_w1h, (const __half*)p_w3h);
    k_down_routed_tc<<<dim3(H / 64,  T / 128, E), 256, SM_GEMM>>>((const __half*)p_w2h, out);

    k_up_shared_tc<<<dim3(IS / 32, T / 128), 256, SM_UP>>>((const __half*)p_xh, (const __half*)p_sw1h, (const __half*)p_sw3h);
    k_final_tc    <<<dim3(H / 64,  T / 128), 256, SM_GEMM>>>((const __half*)p_sw2h, out);
}